// round 8
// baseline (speedup 1.0000x reference)
#include <cuda_runtime.h>
#include <cstdint>

#define NN 100000
#define MAXE 1600000
#define FEAT 128
#define NB_MAX ((NN + 1023) / 1024)

typedef unsigned long long u64;

// ---------------- device scratch (no allocs allowed) ----------------
__device__ float g_msg[(size_t)NN * FEAT];
__device__ float g_h[(size_t)NN * FEAT];
__device__ float g_acc[(size_t)NN * FEAT];   // self-GEMM output (+bias)
__device__ int   g_cnt[NN];
__device__ int   g_cnt2[NN];
__device__ int   g_scanTmp[NN];
__device__ int   g_col[MAXE];
__device__ u64   g_tile[NB_MAX];
__device__ int   g_ctr[4];                   // work-queue counters

#define FLAG_PARTIAL 1ULL
#define FLAG_INCL    2ULL

// ================= zero =================
__global__ void zero_kernel(int n, int nb) {
    int i = blockIdx.x * blockDim.x + threadIdx.x;
    if (i < n) { g_cnt[i] = 0; g_cnt2[i] = 0; }
    if (i < nb) g_tile[i] = 0;
    if (i < 4) g_ctr[i] = 0;
}

// ================= histogram =================
__global__ void hist_kernel(const int* __restrict__ dst, int nE) {
    int i = blockIdx.x * blockDim.x + threadIdx.x;
    if (i < nE) atomicAdd(&g_cnt[__ldg(dst + i)], 1);
}

// ================= single-pass scan (decoupled lookback) =================
__global__ __launch_bounds__(1024)
void scan_kernel(int n) {
    __shared__ int sh[1024];
    __shared__ int s_prefix;
    const int b = blockIdx.x;
    const int t = threadIdx.x;
    const int i = b * 1024 + t;

    int v = (i < n) ? g_cnt[i] : 0;
    sh[t] = v;
    __syncthreads();
#pragma unroll
    for (int off = 1; off < 1024; off <<= 1) {
        int tv = (t >= off) ? sh[t - off] : 0;
        __syncthreads();
        sh[t] += tv;
        __syncthreads();
    }
    int total = sh[1023];

    if (b == 0) {
        if (t == 0) {
            s_prefix = 0;
            atomicExch(&g_tile[0], (FLAG_INCL << 32) | (unsigned)total);
        }
    } else {
        if (t == 0)
            atomicExch(&g_tile[b], (FLAG_PARTIAL << 32) | (unsigned)total);
        if (t < 32) {
            int lane = t;
            int offset = b - 1;
            int prefix = 0;
            for (;;) {
                int idx = offset - lane;
                u64 st = (idx >= 0) ? atomicAdd(&g_tile[idx], 0ULL)
                                    : (FLAG_INCL << 32);
                unsigned rdy = __ballot_sync(0xffffffffu, (st >> 32) != 0);
                if (rdy != 0xffffffffu) continue;
                unsigned inclm = __ballot_sync(0xffffffffu, (st >> 32) == FLAG_INCL);
                int val = (int)(unsigned)st;
                if (inclm) {
                    int L = __ffs(inclm) - 1;
                    int c = (lane <= L) ? val : 0;
#pragma unroll
                    for (int o = 16; o; o >>= 1) c += __shfl_xor_sync(0xffffffffu, c, o);
                    prefix += c;
                    break;
                } else {
                    int c = val;
#pragma unroll
                    for (int o = 16; o; o >>= 1) c += __shfl_xor_sync(0xffffffffu, c, o);
                    prefix += c;
                    offset -= 32;
                }
            }
            if (lane == 0) {
                s_prefix = prefix;
                atomicExch(&g_tile[b], (FLAG_INCL << 32) | (unsigned)(prefix + total));
            }
        }
    }
    __syncthreads();
    if (i < n) g_scanTmp[i] = sh[t] + s_prefix;
}

// ================= fill CSR columns =================
__global__ void fill_kernel(const int* __restrict__ src,
                            const int* __restrict__ dst, int nE) {
    int i = blockIdx.x * blockDim.x + threadIdx.x;
    if (i >= nE) return;
    int d = __ldg(dst + i);
    int base = __ldg(g_scanTmp + d) - __ldg(g_cnt + d);
    int off = atomicAdd(&g_cnt2[d], 1);
    g_col[base + off] = __ldg(src + i);
}

// ================= packed-fma helpers =================
__device__ __forceinline__ void fma2(u64& d, u64 a, u64 b) {
    asm("fma.rn.f32x2 %0, %1, %2, %0;" : "+l"(d) : "l"(a), "l"(b));
}
__device__ __forceinline__ u64 dup2(float x) {
    u64 r; asm("mov.b64 %0, {%1, %1};" : "=l"(r) : "f"(x)); return r;
}
__device__ __forceinline__ void unpack2(u64 v, float& lo, float& hi) {
    asm("mov.b64 {%0, %1}, %2;" : "=f"(lo), "=f"(hi) : "l"(v));
}

// ================= warp gather-mean for one node =================
__device__ __forceinline__ void gather_one(const float* __restrict__ feat,
                                           int node, int lane) {
    int end = __ldg(g_scanTmp + node);
    int deg = __ldg(g_cnt + node);
    int beg = end - deg;
    float4 acc = make_float4(0.f, 0.f, 0.f, 0.f);
    int i = beg;
    for (; i + 4 <= end; i += 4) {
        int s0 = __ldg(g_col + i);
        int s1 = __ldg(g_col + i + 1);
        int s2 = __ldg(g_col + i + 2);
        int s3 = __ldg(g_col + i + 3);
        float4 a = __ldg((const float4*)(feat + (size_t)s0 * FEAT) + lane);
        float4 b = __ldg((const float4*)(feat + (size_t)s1 * FEAT) + lane);
        float4 c = __ldg((const float4*)(feat + (size_t)s2 * FEAT) + lane);
        float4 d = __ldg((const float4*)(feat + (size_t)s3 * FEAT) + lane);
        acc.x += (a.x + b.x) + (c.x + d.x);
        acc.y += (a.y + b.y) + (c.y + d.y);
        acc.z += (a.z + b.z) + (c.z + d.z);
        acc.w += (a.w + b.w) + (c.w + d.w);
    }
    for (; i < end; i++) {
        int s0 = __ldg(g_col + i);
        float4 a = __ldg((const float4*)(feat + (size_t)s0 * FEAT) + lane);
        acc.x += a.x; acc.y += a.y; acc.z += a.z; acc.w += a.w;
    }
    float inv = 1.0f / (float)max(deg, 1);
    acc.x *= inv; acc.y *= inv; acc.z *= inv; acc.w *= inv;
    *((float4*)(g_msg + (size_t)node * FEAT) + lane) = acc;
}

// GEMM tiling shared by phase/neigh kernels: 512 thr, tile 128x128, K=128.
// warp: wr=wid&3 rows wr*32..+31, wc=wid>>2 cols wc*32..+31
// lane: lrow=lane>>1 (2 rows), lcol=lane&1 (16 cols)
#define PH_SMEM 98304     // sW 64KB + sIn 32KB
#define NE_SMEM 107520    // sW 64KB + sIn 32KB + sRed 8KB + sWf 1KB + pad

#define GEMM_COMPUTE(SWBASE)                                                          \
    _Pragma("unroll 2")                                                               \
    for (int k = 0; k < 64; k++) {                                                    \
        float2 av = *(const float2*)(sIn + k * 128 + wr * 32 + lrow * 2);             \
        u64 a0 = dup2(av.x), a1 = dup2(av.y);                                         \
        const u64* wq = (const u64*)((SWBASE) + k * 128 + colb);                      \
        u64 w0 = wq[0], w1 = wq[1], w2 = wq[2], w3 = wq[3];                           \
        u64 w4 = wq[4], w5 = wq[5], w6 = wq[6], w7 = wq[7];                           \
        fma2(acc[0][0], a0, w0); fma2(acc[0][1], a0, w1); fma2(acc[0][2], a0, w2);    \
        fma2(acc[0][3], a0, w3); fma2(acc[0][4], a0, w4); fma2(acc[0][5], a0, w5);    \
        fma2(acc[0][6], a0, w6); fma2(acc[0][7], a0, w7);                             \
        fma2(acc[1][0], a1, w0); fma2(acc[1][1], a1, w1); fma2(acc[1][2], a1, w2);    \
        fma2(acc[1][3], a1, w3); fma2(acc[1][4], a1, w4); fma2(acc[1][5], a1, w5);    \
        fma2(acc[1][6], a1, w6); fma2(acc[1][7], a1, w7);                             \
    }

extern __shared__ char smc[];

// ============ phase kernel: self-GEMM tiles + gather, one work queue ============
__global__ __launch_bounds__(512, 1)
void phase_kernel(const float* __restrict__ X,
                  const float* __restrict__ Wself,
                  const float* __restrict__ bias,
                  int n, int nTiles, int nItems, int ctrIdx) {
    float* sW  = (float*)smc;            // [128][128]
    float* sIn = (float*)(smc + 65536);  // [64][128]
    __shared__ int s_item;

    const int tid  = threadIdx.x;
    const int lane = tid & 31;
    const int wid  = tid >> 5;
    const int wr   = wid & 3;
    const int wc   = wid >> 2;
    const int lrow = lane >> 1;
    const int lcol = lane & 1;
    const int colb = wc * 32 + lcol * 16;
    const int arow = tid & 127;
    const int aq   = tid >> 7;           // 0..3

    // stage Wself once (128x128)
#pragma unroll
    for (int p = 0; p < 8; p++) {
        int idx = p * 512 + tid;          // float4 idx 0..4095
        int k   = idx >> 5;
        int c4  = (idx & 31) * 4;
        *(float4*)(sW + k * 128 + c4) = __ldg((const float4*)(Wself + (size_t)k * FEAT + c4));
    }
    float bv[16];
#pragma unroll
    for (int q = 0; q < 16; q++) bv[q] = __ldg(bias + colb + q);
    __syncthreads();

    for (;;) {
        if (tid == 0) s_item = atomicAdd(&g_ctr[ctrIdx], 1);
        __syncthreads();
        const int t = s_item;
        __syncthreads();
        if (t >= nItems) break;

        if (t % 9 == 0) {
            // ---------- self-GEMM tile ----------
            const int row0 = (t / 9) * 128;
            u64 acc[2][8];
#pragma unroll
            for (int i = 0; i < 2; i++)
#pragma unroll
                for (int j = 0; j < 8; j++) acc[i][j] = 0ull;

            int grow = row0 + arow;
            bool ok = grow < n;
            float4 pf[4];
            {
                const float4* ap = (const float4*)(X + (size_t)grow * FEAT + aq * 16);
#pragma unroll
                for (int j = 0; j < 4; j++)
                    pf[j] = ok ? __ldg(ap + j) : make_float4(0.f, 0.f, 0.f, 0.f);
            }
            for (int ch = 0; ch < 2; ch++) {
#pragma unroll
                for (int j = 0; j < 4; j++) {
                    int kl = aq * 16 + j * 4;
                    sIn[(kl + 0) * 128 + arow] = pf[j].x;
                    sIn[(kl + 1) * 128 + arow] = pf[j].y;
                    sIn[(kl + 2) * 128 + arow] = pf[j].z;
                    sIn[(kl + 3) * 128 + arow] = pf[j].w;
                }
                __syncthreads();
                if (ch == 0) {
                    const float4* ap = (const float4*)(X + (size_t)grow * FEAT + 64 + aq * 16);
#pragma unroll
                    for (int j = 0; j < 4; j++)
                        pf[j] = ok ? __ldg(ap + j) : make_float4(0.f, 0.f, 0.f, 0.f);
                }
                const float* swb = sW + ch * 64 * 128;
                GEMM_COMPUTE(swb)
                __syncthreads();
            }
            // epilogue: +bias, store to g_acc (no relu)
#pragma unroll
            for (int rr = 0; rr < 2; rr++) {
                int r = row0 + wr * 32 + lrow * 2 + rr;
                if (r >= n) continue;
                float o[16];
#pragma unroll
                for (int j = 0; j < 8; j++) {
                    float lo, hi; unpack2(acc[rr][j], lo, hi);
                    o[2 * j] = lo + bv[2 * j]; o[2 * j + 1] = hi + bv[2 * j + 1];
                }
                float4* dp = (float4*)(g_acc + (size_t)r * FEAT + colb);
                dp[0] = make_float4(o[0],  o[1],  o[2],  o[3]);
                dp[1] = make_float4(o[4],  o[5],  o[6],  o[7]);
                dp[2] = make_float4(o[8],  o[9],  o[10], o[11]);
                dp[3] = make_float4(o[12], o[13], o[14], o[15]);
            }
        } else {
            // ---------- gather group: 16 nodes, warp per node ----------
            int g = t - 1 - t / 9;
            int node = g * 16 + wid;
            if (node < n) gather_one(X, node, lane);
        }
    }
}

// ============ neigh kernel: relu(msg@Wn + g_acc); mode1 fuses final proj ============
__global__ __launch_bounds__(512, 1)
void neigh_kernel(const float* __restrict__ Wn,
                  const float* __restrict__ Wf,
                  const float* __restrict__ bf,
                  float* __restrict__ out2,
                  int n, int nTiles, int ctrIdx, int mode) {
    float*  sW   = (float*)smc;             // [128][128]
    float*  sIn  = (float*)(smc + 65536);   // [64][128]
    float2* sRed = (float2*)(smc + 98304);  // [128][8]
    float*  sWf  = (float*)(smc + 106496);  // [128][2]
    __shared__ int s_item;

    const int tid  = threadIdx.x;
    const int lane = tid & 31;
    const int wid  = tid >> 5;
    const int wr   = wid & 3;
    const int wc   = wid >> 2;
    const int lrow = lane >> 1;
    const int lcol = lane & 1;
    const int colb = wc * 32 + lcol * 16;
    const int arow = tid & 127;
    const int aq   = tid >> 7;

#pragma unroll
    for (int p = 0; p < 8; p++) {
        int idx = p * 512 + tid;
        int k   = idx >> 5;
        int c4  = (idx & 31) * 4;
        *(float4*)(sW + k * 128 + c4) = __ldg((const float4*)(Wn + (size_t)k * FEAT + c4));
    }
    if (mode && tid < 256) sWf[tid] = __ldg(Wf + tid);
    __syncthreads();

    for (;;) {
        if (tid == 0) s_item = atomicAdd(&g_ctr[ctrIdx], 1);
        __syncthreads();
        const int t = s_item;
        __syncthreads();
        if (t >= nTiles) break;
        const int row0 = t * 128;

        u64 acc[2][8];
#pragma unroll
        for (int i = 0; i < 2; i++)
#pragma unroll
            for (int j = 0; j < 8; j++) acc[i][j] = 0ull;

        int grow = row0 + arow;
        bool ok = grow < n;
        float4 pf[4];
        {
            const float4* ap = (const float4*)(g_msg + (size_t)grow * FEAT + aq * 16);
#pragma unroll
            for (int j = 0; j < 4; j++)
                pf[j] = ok ? __ldg(ap + j) : make_float4(0.f, 0.f, 0.f, 0.f);
        }
        for (int ch = 0; ch < 2; ch++) {
#pragma unroll
            for (int j = 0; j < 4; j++) {
                int kl = aq * 16 + j * 4;
                sIn[(kl + 0) * 128 + arow] = pf[j].x;
                sIn[(kl + 1) * 128 + arow] = pf[j].y;
                sIn[(kl + 2) * 128 + arow] = pf[j].z;
                sIn[(kl + 3) * 128 + arow] = pf[j].w;
            }
            __syncthreads();
            if (ch == 0) {
                const float4* ap = (const float4*)(g_msg + (size_t)grow * FEAT + 64 + aq * 16);
#pragma unroll
                for (int j = 0; j < 4; j++)
                    pf[j] = ok ? __ldg(ap + j) : make_float4(0.f, 0.f, 0.f, 0.f);
            }
            const float* swb = sW + ch * 64 * 128;
            GEMM_COMPUTE(swb)
            __syncthreads();
        }

        if (mode == 0) {
            // h = relu(msg@Wn + g_acc)
#pragma unroll
            for (int rr = 0; rr < 2; rr++) {
                int r = row0 + wr * 32 + lrow * 2 + rr;
                if (r >= n) continue;
                const float4* sp = (const float4*)(g_acc + (size_t)r * FEAT + colb);
                float4 s0 = __ldg(sp), s1 = __ldg(sp + 1), s2 = __ldg(sp + 2), s3 = __ldg(sp + 3);
                float sv[16] = {s0.x,s0.y,s0.z,s0.w, s1.x,s1.y,s1.z,s1.w,
                                s2.x,s2.y,s2.z,s2.w, s3.x,s3.y,s3.z,s3.w};
                float o[16];
#pragma unroll
                for (int j = 0; j < 8; j++) {
                    float lo, hi; unpack2(acc[rr][j], lo, hi);
                    o[2 * j]     = fmaxf(lo + sv[2 * j],     0.0f);
                    o[2 * j + 1] = fmaxf(hi + sv[2 * j + 1], 0.0f);
                }
                float4* dp = (float4*)(g_h + (size_t)r * FEAT + colb);
                dp[0] = make_float4(o[0],  o[1],  o[2],  o[3]);
                dp[1] = make_float4(o[4],  o[5],  o[6],  o[7]);
                dp[2] = make_float4(o[8],  o[9],  o[10], o[11]);
                dp[3] = make_float4(o[12], o[13], o[14], o[15]);
            }
        } else {
            // fused final: out = relu(msg@Wn + g_acc) @ Wf + bf
#pragma unroll
            for (int rr = 0; rr < 2; rr++) {
                int r = row0 + wr * 32 + lrow * 2 + rr;
                float p0 = 0.f, p1 = 0.f;
                if (r < n) {
                    const float4* sp = (const float4*)(g_acc + (size_t)r * FEAT + colb);
                    float4 s0 = __ldg(sp), s1 = __ldg(sp + 1), s2 = __ldg(sp + 2), s3 = __ldg(sp + 3);
                    float sv[16] = {s0.x,s0.y,s0.z,s0.w, s1.x,s1.y,s1.z,s1.w,
                                    s2.x,s2.y,s2.z,s2.w, s3.x,s3.y,s3.z,s3.w};
#pragma unroll
                    for (int j = 0; j < 8; j++) {
                        float lo, hi; unpack2(acc[rr][j], lo, hi);
                        float o0 = fmaxf(lo + sv[2 * j],     0.0f);
                        float o1 = fmaxf(hi + sv[2 * j + 1], 0.0f);
                        int c0 = colb + 2 * j, c1 = colb + 2 * j + 1;
                        p0 += o0 * sWf[c0 * 2]     + o1 * sWf[c1 * 2];
                        p1 += o0 * sWf[c0 * 2 + 1] + o1 * sWf[c1 * 2 + 1];
                    }
                }
                sRed[(wr * 32 + lrow * 2 + rr) * 8 + (wc * 2 + lcol)] = make_float2(p0, p1);
            }
            __syncthreads();
            if (tid < 128) {
                int grow2 = row0 + tid;
                float a0 = 0.f, a1 = 0.f;
#pragma unroll
                for (int g2 = 0; g2 < 8; g2++) {
                    float2 v = sRed[tid * 8 + g2];
                    a0 += v.x; a1 += v.y;
                }
                if (grow2 < n) {
                    out2[2 * (size_t)grow2]     = a0 + __ldg(bf);
                    out2[2 * (size_t)grow2 + 1] = a1 + __ldg(bf + 1);
                }
            }
            __syncthreads();
        }
    }
}

// ================= launch =================
extern "C" void kernel_launch(void* const* d_in, const int* in_sizes, int n_in,
                              void* d_out, int out_size) {
    const float* x   = (const float*)d_in[0];
    const float* Ws1 = (const float*)d_in[1];
    const float* Wn1 = (const float*)d_in[2];
    const float* b1  = (const float*)d_in[3];
    const float* Ws2 = (const float*)d_in[4];
    const float* Wn2 = (const float*)d_in[5];
    const float* b2  = (const float*)d_in[6];
    const float* Wf  = (const float*)d_in[7];
    const float* bf  = (const float*)d_in[8];
    const int*   src = (const int*)d_in[9];
    const int*   dst = (const int*)d_in[10];
    float* out = (float*)d_out;

    int n  = in_sizes[0] / FEAT;
    int nE = in_sizes[9];
    int nb = (n + 1023) / 1024;
    int nTiles  = (n + 127) / 128;
    int ngroups = (n + 15) / 16;
    int nItems  = nTiles + ngroups;

    cudaFuncSetAttribute(phase_kernel, cudaFuncAttributeMaxDynamicSharedMemorySize, PH_SMEM);
    cudaFuncSetAttribute(neigh_kernel, cudaFuncAttributeMaxDynamicSharedMemorySize, NE_SMEM);

    void* p_h = 0;
    cudaGetSymbolAddress(&p_h, g_h);
    const float* h = (const float*)p_h;

    // ---- CSR build ----
    zero_kernel<<<(n + 255) / 256, 256>>>(n, nb);
    hist_kernel<<<(nE + 255) / 256, 256>>>(dst, nE);
    scan_kernel<<<nb, 1024>>>(n);
    fill_kernel<<<(nE + 255) / 256, 256>>>(src, dst, nE);

    // layer 1: overlap self-GEMM + gather, then neigh-GEMM
    phase_kernel<<<148, 512, PH_SMEM>>>(x, Ws1, b1, n, nTiles, nItems, 0);
    neigh_kernel<<<148, 512, NE_SMEM>>>(Wn1, Wf, bf, out, n, nTiles, 1, 0);

    // layer 2: same, neigh fuses the final projection
    phase_kernel<<<148, 512, PH_SMEM>>>(h, Ws2, b2, n, nTiles, nItems, 2);
    neigh_kernel<<<148, 512, NE_SMEM>>>(Wn2, Wf, bf, out, n, nTiles, 3, 1);
}

// round 9
// speedup vs baseline: 1.2575x; 1.2575x over previous
#include <cuda_runtime.h>
#include <cstdint>

#define NN 100000
#define MAXE 1600000
#define FEAT 128
#define NB_MAX ((NN + 1023) / 1024)

typedef unsigned long long u64;

// ---------------- device scratch (no allocs allowed) ----------------
__device__ float g_msg[(size_t)NN * FEAT];
__device__ float g_h[(size_t)NN * FEAT];
__device__ int   g_cnt[NN];      // degree per node
__device__ int   g_cnt2[NN];     // fill cursor offset per node
__device__ int   g_scanTmp[NN];  // inclusive prefix of cnt
__device__ int   g_col[MAXE];
__device__ u64   g_tile[NB_MAX]; // lookback tile state: flag<<32 | value
__device__ int   g_ctr[4];       // GEMM tile counters: layer*2 + colHalf

#define FLAG_PARTIAL 1ULL
#define FLAG_INCL    2ULL

// ================= zero =================
__global__ void zero_kernel(int n, int nb) {
    int i = blockIdx.x * blockDim.x + threadIdx.x;
    if (i < n) { g_cnt[i] = 0; g_cnt2[i] = 0; }
    if (i < nb) g_tile[i] = 0;
    if (i < 4) g_ctr[i] = 0;
}

// ================= histogram =================
__global__ void hist_kernel(const int* __restrict__ dst, int nE) {
    int i = blockIdx.x * blockDim.x + threadIdx.x;
    if (i < nE) atomicAdd(&g_cnt[__ldg(dst + i)], 1);
}

// ================= single-pass scan (decoupled lookback) =================
__global__ __launch_bounds__(1024)
void scan_kernel(int n) {
    __shared__ int sh[1024];
    __shared__ int s_prefix;
    const int b = blockIdx.x;
    const int t = threadIdx.x;
    const int i = b * 1024 + t;

    int v = (i < n) ? g_cnt[i] : 0;
    sh[t] = v;
    __syncthreads();
#pragma unroll
    for (int off = 1; off < 1024; off <<= 1) {
        int tv = (t >= off) ? sh[t - off] : 0;
        __syncthreads();
        sh[t] += tv;
        __syncthreads();
    }
    int total = sh[1023];

    if (b == 0) {
        if (t == 0) {
            s_prefix = 0;
            atomicExch(&g_tile[0], (FLAG_INCL << 32) | (unsigned)total);
        }
    } else {
        if (t == 0)
            atomicExch(&g_tile[b], (FLAG_PARTIAL << 32) | (unsigned)total);
        if (t < 32) {
            int lane = t;
            int offset = b - 1;
            int prefix = 0;
            for (;;) {
                int idx = offset - lane;
                u64 st = (idx >= 0) ? atomicAdd(&g_tile[idx], 0ULL)
                                    : (FLAG_INCL << 32);
                unsigned rdy = __ballot_sync(0xffffffffu, (st >> 32) != 0);
                if (rdy != 0xffffffffu) continue;
                unsigned inclm = __ballot_sync(0xffffffffu, (st >> 32) == FLAG_INCL);
                int val = (int)(unsigned)st;
                if (inclm) {
                    int L = __ffs(inclm) - 1;
                    int c = (lane <= L) ? val : 0;
#pragma unroll
                    for (int o = 16; o; o >>= 1) c += __shfl_xor_sync(0xffffffffu, c, o);
                    prefix += c;
                    break;
                } else {
                    int c = val;
#pragma unroll
                    for (int o = 16; o; o >>= 1) c += __shfl_xor_sync(0xffffffffu, c, o);
                    prefix += c;
                    offset -= 32;
                }
            }
            if (lane == 0) {
                s_prefix = prefix;
                atomicExch(&g_tile[b], (FLAG_INCL << 32) | (unsigned)(prefix + total));
            }
        }
    }
    __syncthreads();
    if (i < n) g_scanTmp[i] = sh[t] + s_prefix;
}

// ================= fill CSR columns =================
__global__ void fill_kernel(const int* __restrict__ src,
                            const int* __restrict__ dst, int nE) {
    int i = blockIdx.x * blockDim.x + threadIdx.x;
    if (i >= nE) return;
    int d = __ldg(dst + i);
    int base = __ldg(g_scanTmp + d) - __ldg(g_cnt + d);
    int off = atomicAdd(&g_cnt2[d], 1);
    g_col[base + off] = __ldg(src + i);
}

// ================= gather-mean: warp per node =================
__global__ void gather_kernel(const float* __restrict__ feat, int n) {
    int gw = (int)(((size_t)blockIdx.x * blockDim.x + threadIdx.x) >> 5);
    int lane = threadIdx.x & 31;
    if (gw >= n) return;
    int end = __ldg(g_scanTmp + gw);
    int deg = __ldg(g_cnt + gw);
    int beg = end - deg;
    float4 acc = make_float4(0.f, 0.f, 0.f, 0.f);
    int i = beg;
    for (; i + 4 <= end; i += 4) {
        int s0 = __ldg(g_col + i);
        int s1 = __ldg(g_col + i + 1);
        int s2 = __ldg(g_col + i + 2);
        int s3 = __ldg(g_col + i + 3);
        float4 a = __ldg((const float4*)(feat + (size_t)s0 * FEAT) + lane);
        float4 b = __ldg((const float4*)(feat + (size_t)s1 * FEAT) + lane);
        float4 c = __ldg((const float4*)(feat + (size_t)s2 * FEAT) + lane);
        float4 d = __ldg((const float4*)(feat + (size_t)s3 * FEAT) + lane);
        acc.x += (a.x + b.x) + (c.x + d.x);
        acc.y += (a.y + b.y) + (c.y + d.y);
        acc.z += (a.z + b.z) + (c.z + d.z);
        acc.w += (a.w + b.w) + (c.w + d.w);
    }
    for (; i < end; i++) {
        int s0 = __ldg(g_col + i);
        float4 a = __ldg((const float4*)(feat + (size_t)s0 * FEAT) + lane);
        acc.x += a.x; acc.y += a.y; acc.z += a.z; acc.w += a.w;
    }
    float inv = 1.0f / (float)max(deg, 1);
    acc.x *= inv; acc.y *= inv; acc.z *= inv; acc.w *= inv;
    *((float4*)(g_msg + (size_t)gw * FEAT) + lane) = acc;
}

// ================= persistent SAGE GEMM v7 (2 blocks/SM, col-half split) =================
// 296 blocks x 256 threads, 2 blocks/SM. Each block owns a fixed 64-col half of
// the stacked W (256x64 = 64KB smem, staged once); tiles (128 rows) pulled from
// a per-half atomic counter; A chunks register-prefetched one chunk ahead.
__device__ __forceinline__ void fma2(u64& d, u64 a, u64 b) {
    asm("fma.rn.f32x2 %0, %1, %2, %0;" : "+l"(d) : "l"(a), "l"(b));
}
__device__ __forceinline__ u64 dup2(float x) {
    u64 r; asm("mov.b64 %0, {%1, %1};" : "=l"(r) : "f"(x)); return r;
}
__device__ __forceinline__ void unpack2(u64 v, float& lo, float& hi) {
    asm("mov.b64 {%0, %1}, %2;" : "=f"(lo), "=f"(hi) : "l"(v));
}

#define BR 128
#define SW_OFF  0                 // sW : [256][64] float = 64KB (col half of Wself ‖ Wneigh)
#define SIN_OFF 65536             // sIn: [64][128] float = 32KB (A chunk, k-major)
#define GEMM_SMEM_BYTES 98304

extern __shared__ char smc[];

__global__ __launch_bounds__(256, 2)
void sage_gemm_kernel(const float* __restrict__ X,
                      const float* __restrict__ Wself,
                      const float* __restrict__ Wneigh,
                      const float* __restrict__ bias,
                      float* __restrict__ OUT, int n, int nTiles, int ctrBase) {
    float* sW  = (float*)(smc + SW_OFF);    // sW[k*64 + c], k=0..255, c local
    float* sIn = (float*)(smc + SIN_OFF);   // sIn[kl*128 + row]
    __shared__ int s_tile;

    const int tid  = threadIdx.x;
    const int lane = tid & 31;
    const int wid  = tid >> 5;               // 0..7
    const int wr   = wid & 1;                // rows wr*64 .. +63
    const int wc   = wid >> 1;               // local cols wc*16 .. +15
    const int lrow = lane >> 1;              // rows wr*64 + lrow*4 .. +3
    const int lcol = lane & 1;               // local cols wc*16 + lcol*8 .. +7
    const int colh = blockIdx.x & 1;         // column half (fixed per block)
    const int colb = wc * 16 + lcol * 8;     // local col base (0..56)
    const int gcolb = colh * 64 + colb;      // global col base

    // ---- stage W col-half once: k<128 -> Wself[k], k>=128 -> Wneigh[k-128] ----
#pragma unroll
    for (int p = 0; p < 16; p++) {
        int idx = p * 256 + tid;             // float4 idx 0..4095
        int k   = idx >> 4;                  // 16 float4 per 64-float k-row
        int c4  = (idx & 15) * 4;
        const float* wsrc = (k < 128) ? (Wself + (size_t)k * FEAT)
                                      : (Wneigh + (size_t)(k - 128) * FEAT);
        *(float4*)(sW + k * 64 + c4) = __ldg((const float4*)(wsrc + colh * 64 + c4));
    }
    float bv[8];
#pragma unroll
    for (int q = 0; q < 8; q++) bv[q] = __ldg(bias + gcolb + q);
    __syncthreads();

    const int arow  = tid >> 1;              // staging row, 0..127
    const int akoff = (tid & 1) * 32;        // staging k half

    const int myCtr = ctrBase + colh;

    for (;;) {
        if (tid == 0) s_tile = atomicAdd(&g_ctr[myCtr], 1);
        __syncthreads();
        const int t = s_tile;
        __syncthreads();
        if (t >= nTiles) break;
        const int row0 = t * BR;

        u64 acc[4][4];
#pragma unroll
        for (int i = 0; i < 4; i++)
#pragma unroll
            for (int j = 0; j < 4; j++) acc[i][j] = 0ull;

        // prefetch chunk 0 (X, k 0..63)
        float4 pf[8];
        {
            int grow = row0 + arow;
            bool ok = grow < n;
            const float4* ap = (const float4*)(X + (size_t)grow * FEAT + akoff);
#pragma unroll
            for (int j = 0; j < 8; j++)
                pf[j] = ok ? __ldg(ap + j) : make_float4(0.f, 0.f, 0.f, 0.f);
        }

        for (int ch = 0; ch < 4; ch++) {
            // ---- store prefetched chunk to sIn (transposed) ----
#pragma unroll
            for (int j = 0; j < 8; j++) {
                int kl = akoff + j * 4;
                sIn[(kl + 0) * 128 + arow] = pf[j].x;
                sIn[(kl + 1) * 128 + arow] = pf[j].y;
                sIn[(kl + 2) * 128 + arow] = pf[j].z;
                sIn[(kl + 3) * 128 + arow] = pf[j].w;
            }
            __syncthreads();

            // ---- prefetch next chunk ----
            if (ch < 3) {
                const float* srcp = (ch < 1) ? X : g_msg;   // (ch+1)<2 ? X : msg
                int koff = ((ch + 1) & 1) * 64;
                int grow = row0 + arow;
                bool ok = grow < n;
                const float4* ap = (const float4*)(srcp + (size_t)grow * FEAT + koff + akoff);
#pragma unroll
                for (int j = 0; j < 8; j++)
                    pf[j] = ok ? __ldg(ap + j) : make_float4(0.f, 0.f, 0.f, 0.f);
            }

            // ---- compute 64 k-steps ----
            const int wbase = ch * 64;
#pragma unroll 2
            for (int k = 0; k < 64; k++) {
                float4 av = *(const float4*)(sIn + k * 128 + wr * 64 + lrow * 4);
                u64 a0 = dup2(av.x), a1 = dup2(av.y), a2 = dup2(av.z), a3 = dup2(av.w);
                const u64* wq = (const u64*)(sW + (wbase + k) * 64 + colb);
                u64 w0 = wq[0], w1 = wq[1], w2 = wq[2], w3 = wq[3];
                fma2(acc[0][0], a0, w0); fma2(acc[0][1], a0, w1); fma2(acc[0][2], a0, w2); fma2(acc[0][3], a0, w3);
                fma2(acc[1][0], a1, w0); fma2(acc[1][1], a1, w1); fma2(acc[1][2], a1, w2); fma2(acc[1][3], a1, w3);
                fma2(acc[2][0], a2, w0); fma2(acc[2][1], a2, w1); fma2(acc[2][2], a2, w2); fma2(acc[2][3], a2, w3);
                fma2(acc[3][0], a3, w0); fma2(acc[3][1], a3, w1); fma2(acc[3][2], a3, w2); fma2(acc[3][3], a3, w3);
            }
            __syncthreads();
        }

        // ---- epilogue: bias + relu + store 8 cols per thread ----
#pragma unroll
        for (int i = 0; i < 4; i++) {
            int grow = row0 + wr * 64 + lrow * 4 + i;
            if (grow >= n) continue;
            float o[8];
#pragma unroll
            for (int j = 0; j < 4; j++) unpack2(acc[i][j], o[2 * j], o[2 * j + 1]);
#pragma unroll
            for (int q = 0; q < 8; q++) o[q] = fmaxf(o[q] + bv[q], 0.0f);
            float4* dp = (float4*)(OUT + (size_t)grow * FEAT + gcolb);
            dp[0] = make_float4(o[0], o[1], o[2], o[3]);
            dp[1] = make_float4(o[4], o[5], o[6], o[7]);
        }
    }
}

// ================= final projection =================
__global__ void final_kernel(const float* __restrict__ Wf,
                             const float* __restrict__ bf,
                             float* __restrict__ out, int n) {
    int gw = (int)(((size_t)blockIdx.x * blockDim.x + threadIdx.x) >> 5);
    int lane = threadIdx.x & 31;
    if (gw >= n) return;
    float4 h = __ldg((const float4*)(g_h + (size_t)gw * FEAT) + lane);
    float s0 = 0.f, s1 = 0.f;
    const float* hv = (const float*)&h;
#pragma unroll
    for (int i = 0; i < 4; i++) {
        float2 w = __ldg((const float2*)Wf + lane * 4 + i);
        s0 += hv[i] * w.x;
        s1 += hv[i] * w.y;
    }
#pragma unroll
    for (int off = 16; off; off >>= 1) {
        s0 += __shfl_down_sync(0xffffffffu, s0, off);
        s1 += __shfl_down_sync(0xffffffffu, s1, off);
    }
    if (lane == 0) {
        out[2 * (size_t)gw]     = s0 + __ldg(bf);
        out[2 * (size_t)gw + 1] = s1 + __ldg(bf + 1);
    }
}

// ================= launch =================
extern "C" void kernel_launch(void* const* d_in, const int* in_sizes, int n_in,
                              void* d_out, int out_size) {
    const float* x   = (const float*)d_in[0];
    const float* Ws1 = (const float*)d_in[1];
    const float* Wn1 = (const float*)d_in[2];
    const float* b1  = (const float*)d_in[3];
    const float* Ws2 = (const float*)d_in[4];
    const float* Wn2 = (const float*)d_in[5];
    const float* b2  = (const float*)d_in[6];
    const float* Wf  = (const float*)d_in[7];
    const float* bf  = (const float*)d_in[8];
    const int*   src = (const int*)d_in[9];
    const int*   dst = (const int*)d_in[10];
    float* out = (float*)d_out;

    int n  = in_sizes[0] / FEAT;
    int nE = in_sizes[9];
    int nb = (n + 1023) / 1024;
    int nTiles = (n + BR - 1) / BR;

    cudaFuncSetAttribute(sage_gemm_kernel,
                         cudaFuncAttributeMaxDynamicSharedMemorySize, GEMM_SMEM_BYTES);

    void* p_h = 0;
    cudaGetSymbolAddress(&p_h, g_h);
    float* h = (float*)p_h;

    // ---- CSR build ----
    zero_kernel<<<(n + 255) / 256, 256>>>(n, nb);
    hist_kernel<<<(nE + 255) / 256, 256>>>(dst, nE);
    scan_kernel<<<nb, 1024>>>(n);
    fill_kernel<<<(nE + 255) / 256, 256>>>(src, dst, nE);

    int gatherBlocks = (n + 7) / 8;

    // layer 1
    gather_kernel<<<gatherBlocks, 256>>>(x, n);
    sage_gemm_kernel<<<296, 256, GEMM_SMEM_BYTES>>>(x, Ws1, Wn1, b1, h, n, nTiles, 0);

    // layer 2
    gather_kernel<<<gatherBlocks, 256>>>(h, n);
    sage_gemm_kernel<<<296, 256, GEMM_SMEM_BYTES>>>(h, Ws2, Wn2, b2, h, n, nTiles, 2);

    // final projection
    final_kernel<<<(n + 7) / 8, 256>>>(Wf, bf, out, n);
}

// round 10
// speedup vs baseline: 1.3062x; 1.0387x over previous
#include <cuda_runtime.h>
#include <cstdint>

#define NN 100000
#define MAXE 1600000
#define FEAT 128
#define NB_MAX ((NN + 1023) / 1024)

typedef unsigned long long u64;

// ---------------- device scratch (no allocs allowed) ----------------
__device__ float g_msg[(size_t)NN * FEAT];
__device__ float g_h[(size_t)NN * FEAT];
__device__ int   g_cnt[NN];      // degree per node
__device__ int   g_cnt2[NN];     // fill cursor offset per node
__device__ int   g_scanTmp[NN];  // inclusive prefix of cnt
__device__ int   g_col[MAXE];
__device__ u64   g_tile[NB_MAX]; // lookback tile state: flag<<32 | value
__device__ int   g_ctr[4];       // GEMM tile counters per layer

#define FLAG_PARTIAL 1ULL
#define FLAG_INCL    2ULL

// ================= zero =================
__global__ void zero_kernel(int n, int nb) {
    int i = blockIdx.x * blockDim.x + threadIdx.x;
    if (i < n) { g_cnt[i] = 0; g_cnt2[i] = 0; }
    if (i < nb) g_tile[i] = 0;
    if (i < 4) g_ctr[i] = 0;
}

// ================= histogram =================
__global__ void hist_kernel(const int* __restrict__ dst, int nE) {
    int i = blockIdx.x * blockDim.x + threadIdx.x;
    if (i < nE) atomicAdd(&g_cnt[__ldg(dst + i)], 1);
}

// ================= single-pass scan (decoupled lookback) =================
__global__ __launch_bounds__(1024)
void scan_kernel(int n) {
    __shared__ int sh[1024];
    __shared__ int s_prefix;
    const int b = blockIdx.x;
    const int t = threadIdx.x;
    const int i = b * 1024 + t;

    int v = (i < n) ? g_cnt[i] : 0;
    sh[t] = v;
    __syncthreads();
#pragma unroll
    for (int off = 1; off < 1024; off <<= 1) {
        int tv = (t >= off) ? sh[t - off] : 0;
        __syncthreads();
        sh[t] += tv;
        __syncthreads();
    }
    int total = sh[1023];

    if (b == 0) {
        if (t == 0) {
            s_prefix = 0;
            atomicExch(&g_tile[0], (FLAG_INCL << 32) | (unsigned)total);
        }
    } else {
        if (t == 0)
            atomicExch(&g_tile[b], (FLAG_PARTIAL << 32) | (unsigned)total);
        if (t < 32) {
            int lane = t;
            int offset = b - 1;
            int prefix = 0;
            for (;;) {
                int idx = offset - lane;
                u64 st = (idx >= 0) ? atomicAdd(&g_tile[idx], 0ULL)
                                    : (FLAG_INCL << 32);
                unsigned rdy = __ballot_sync(0xffffffffu, (st >> 32) != 0);
                if (rdy != 0xffffffffu) continue;
                unsigned inclm = __ballot_sync(0xffffffffu, (st >> 32) == FLAG_INCL);
                int val = (int)(unsigned)st;
                if (inclm) {
                    int L = __ffs(inclm) - 1;
                    int c = (lane <= L) ? val : 0;
#pragma unroll
                    for (int o = 16; o; o >>= 1) c += __shfl_xor_sync(0xffffffffu, c, o);
                    prefix += c;
                    break;
                } else {
                    int c = val;
#pragma unroll
                    for (int o = 16; o; o >>= 1) c += __shfl_xor_sync(0xffffffffu, c, o);
                    prefix += c;
                    offset -= 32;
                }
            }
            if (lane == 0) {
                s_prefix = prefix;
                atomicExch(&g_tile[b], (FLAG_INCL << 32) | (unsigned)(prefix + total));
            }
        }
    }
    __syncthreads();
    if (i < n) g_scanTmp[i] = sh[t] + s_prefix;
}

// ================= fill CSR columns =================
__global__ void fill_kernel(const int* __restrict__ src,
                            const int* __restrict__ dst, int nE) {
    int i = blockIdx.x * blockDim.x + threadIdx.x;
    if (i >= nE) return;
    int d = __ldg(dst + i);
    int base = __ldg(g_scanTmp + d) - __ldg(g_cnt + d);
    int off = atomicAdd(&g_cnt2[d], 1);
    g_col[base + off] = __ldg(src + i);
}

// ================= gather-mean: warp per node =================
__global__ void gather_kernel(const float* __restrict__ feat, int n) {
    int gw = (int)(((size_t)blockIdx.x * blockDim.x + threadIdx.x) >> 5);
    int lane = threadIdx.x & 31;
    if (gw >= n) return;
    int end = __ldg(g_scanTmp + gw);
    int deg = __ldg(g_cnt + gw);
    int beg = end - deg;
    float4 acc = make_float4(0.f, 0.f, 0.f, 0.f);
    int i = beg;
    for (; i + 4 <= end; i += 4) {
        int s0 = __ldg(g_col + i);
        int s1 = __ldg(g_col + i + 1);
        int s2 = __ldg(g_col + i + 2);
        int s3 = __ldg(g_col + i + 3);
        float4 a = __ldg((const float4*)(feat + (size_t)s0 * FEAT) + lane);
        float4 b = __ldg((const float4*)(feat + (size_t)s1 * FEAT) + lane);
        float4 c = __ldg((const float4*)(feat + (size_t)s2 * FEAT) + lane);
        float4 d = __ldg((const float4*)(feat + (size_t)s3 * FEAT) + lane);
        acc.x += (a.x + b.x) + (c.x + d.x);
        acc.y += (a.y + b.y) + (c.y + d.y);
        acc.z += (a.z + b.z) + (c.z + d.z);
        acc.w += (a.w + b.w) + (c.w + d.w);
    }
    for (; i < end; i++) {
        int s0 = __ldg(g_col + i);
        float4 a = __ldg((const float4*)(feat + (size_t)s0 * FEAT) + lane);
        acc.x += a.x; acc.y += a.y; acc.z += a.z; acc.w += a.w;
    }
    float inv = 1.0f / (float)max(deg, 1);
    acc.x *= inv; acc.y *= inv; acc.z *= inv; acc.w *= inv;
    *((float4*)(g_msg + (size_t)gw * FEAT) + lane) = acc;
}

// ================= persistent SAGE GEMM v8 =================
// 148 blocks x 512 threads, 1 block/SM (16 warps = 4/SMSP).
// Full stacked W (256x128 = 128KB) resident in smem; tile 128x128;
// per-thread 2 rows x 16 cols; A chunks register-prefetched (pf[4]).
__device__ __forceinline__ void fma2(u64& d, u64 a, u64 b) {
    asm("fma.rn.f32x2 %0, %1, %2, %0;" : "+l"(d) : "l"(a), "l"(b));
}
__device__ __forceinline__ u64 dup2(float x) {
    u64 r; asm("mov.b64 %0, {%1, %1};" : "=l"(r) : "f"(x)); return r;
}
__device__ __forceinline__ void unpack2(u64 v, float& lo, float& hi) {
    asm("mov.b64 {%0, %1}, %2;" : "=f"(lo), "=f"(hi) : "l"(v));
}

#define BR 128
#define SW_OFF  0                 // sW : [256][128] float = 128KB
#define SIN_OFF 131072            // sIn: [64][128] float  = 32KB
#define GEMM_SMEM_BYTES 163840

extern __shared__ char smc[];

__global__ __launch_bounds__(512, 1)
void sage_gemm_kernel(const float* __restrict__ X,
                      const float* __restrict__ Wself,
                      const float* __restrict__ Wneigh,
                      const float* __restrict__ bias,
                      float* __restrict__ OUT, int n, int nTiles, int ctrIdx) {
    float* sW  = (float*)(smc + SW_OFF);    // sW[k*128 + col], k = 0..255
    float* sIn = (float*)(smc + SIN_OFF);   // sIn[kl*128 + row]
    __shared__ int s_tile;

    const int tid  = threadIdx.x;
    const int lane = tid & 31;
    const int wid  = tid >> 5;               // 0..15
    const int wr   = wid & 3;                // rows wr*32 .. +31
    const int wc   = wid >> 2;               // cols wc*32 .. +31
    const int lrow = lane >> 1;              // 0..15 -> rows wr*32 + lrow*2 .. +1
    const int lcol = lane & 1;               // cols wc*32 + lcol*16 .. +15
    const int colb = wc * 32 + lcol * 16;

    // ---- stage full W once: k<128 -> Wself[k], k>=128 -> Wneigh[k-128] ----
#pragma unroll
    for (int p = 0; p < 16; p++) {
        int idx = p * 512 + tid;             // float4 index, 0..8191
        int k   = idx >> 5;
        int c4  = (idx & 31) * 4;
        const float* wsrc = (k < 128) ? (Wself + (size_t)k * FEAT)
                                      : (Wneigh + (size_t)(k - 128) * FEAT);
        *(float4*)(sW + k * 128 + c4) = __ldg((const float4*)(wsrc + c4));
    }
    float bv[16];
#pragma unroll
    for (int q = 0; q < 16; q++) bv[q] = __ldg(bias + colb + q);
    __syncthreads();

    const int arow  = tid >> 2;              // staging row, 0..127
    const int akoff = (tid & 3) * 16;        // staging k quarter

    for (;;) {
        if (tid == 0) s_tile = atomicAdd(&g_ctr[ctrIdx], 1);
        __syncthreads();
        const int t = s_tile;
        __syncthreads();                     // allow s_tile reuse next iter
        if (t >= nTiles) break;
        const int row0 = t * BR;

        u64 acc[2][8];
#pragma unroll
        for (int i = 0; i < 2; i++)
#pragma unroll
            for (int j = 0; j < 8; j++) acc[i][j] = 0ull;

        // prefetch chunk 0 (X, k 0..63)
        float4 pf[4];
        {
            int grow = row0 + arow;
            bool ok = grow < n;
            const float4* ap = (const float4*)(X + (size_t)grow * FEAT + akoff);
#pragma unroll
            for (int j = 0; j < 4; j++)
                pf[j] = ok ? __ldg(ap + j) : make_float4(0.f, 0.f, 0.f, 0.f);
        }

        for (int ch = 0; ch < 4; ch++) {
            // ---- store prefetched chunk to sIn (transposed) ----
#pragma unroll
            for (int j = 0; j < 4; j++) {
                int kl = akoff + j * 4;
                sIn[(kl + 0) * 128 + arow] = pf[j].x;
                sIn[(kl + 1) * 128 + arow] = pf[j].y;
                sIn[(kl + 2) * 128 + arow] = pf[j].z;
                sIn[(kl + 3) * 128 + arow] = pf[j].w;
            }
            __syncthreads();

            // ---- prefetch next chunk ----
            if (ch < 3) {
                const float* srcp = (ch < 1) ? X : g_msg;   // (ch+1)<2 ? X : msg
                int koff = ((ch + 1) & 1) * 64;
                int grow = row0 + arow;
                bool ok = grow < n;
                const float4* ap = (const float4*)(srcp + (size_t)grow * FEAT + koff + akoff);
#pragma unroll
                for (int j = 0; j < 4; j++)
                    pf[j] = ok ? __ldg(ap + j) : make_float4(0.f, 0.f, 0.f, 0.f);
            }

            // ---- compute 64 k-steps ----
            const int wbase = ch * 64;
#pragma unroll 4
            for (int k = 0; k < 64; k++) {
                float2 av = *(const float2*)(sIn + k * 128 + wr * 32 + lrow * 2);
                u64 a0 = dup2(av.x), a1 = dup2(av.y);
                const u64* wq = (const u64*)(sW + (wbase + k) * 128 + colb);
                u64 w0 = wq[0], w1 = wq[1], w2 = wq[2], w3 = wq[3];
                u64 w4 = wq[4], w5 = wq[5], w6 = wq[6], w7 = wq[7];
                fma2(acc[0][0], a0, w0); fma2(acc[0][1], a0, w1); fma2(acc[0][2], a0, w2); fma2(acc[0][3], a0, w3);
                fma2(acc[0][4], a0, w4); fma2(acc[0][5], a0, w5); fma2(acc[0][6], a0, w6); fma2(acc[0][7], a0, w7);
                fma2(acc[1][0], a1, w0); fma2(acc[1][1], a1, w1); fma2(acc[1][2], a1, w2); fma2(acc[1][3], a1, w3);
                fma2(acc[1][4], a1, w4); fma2(acc[1][5], a1, w5); fma2(acc[1][6], a1, w6); fma2(acc[1][7], a1, w7);
            }
            __syncthreads();
        }

        // ---- epilogue: bias + relu + store 16 cols per thread ----
#pragma unroll
        for (int i = 0; i < 2; i++) {
            int grow = row0 + wr * 32 + lrow * 2 + i;
            if (grow >= n) continue;
            float o[16];
#pragma unroll
            for (int j = 0; j < 8; j++) unpack2(acc[i][j], o[2 * j], o[2 * j + 1]);
#pragma unroll
            for (int q = 0; q < 16; q++) o[q] = fmaxf(o[q] + bv[q], 0.0f);
            float4* dp = (float4*)(OUT + (size_t)grow * FEAT + colb);
            dp[0] = make_float4(o[0],  o[1],  o[2],  o[3]);
            dp[1] = make_float4(o[4],  o[5],  o[6],  o[7]);
            dp[2] = make_float4(o[8],  o[9],  o[10], o[11]);
            dp[3] = make_float4(o[12], o[13], o[14], o[15]);
        }
    }
}

// ================= final projection =================
__global__ void final_kernel(const float* __restrict__ Wf,
                             const float* __restrict__ bf,
                             float* __restrict__ out, int n) {
    int gw = (int)(((size_t)blockIdx.x * blockDim.x + threadIdx.x) >> 5);
    int lane = threadIdx.x & 31;
    if (gw >= n) return;
    float4 h = __ldg((const float4*)(g_h + (size_t)gw * FEAT) + lane);
    float s0 = 0.f, s1 = 0.f;
    const float* hv = (const float*)&h;
#pragma unroll
    for (int i = 0; i < 4; i++) {
        float2 w = __ldg((const float2*)Wf + lane * 4 + i);
        s0 += hv[i] * w.x;
        s1 += hv[i] * w.y;
    }
#pragma unroll
    for (int off = 16; off; off >>= 1) {
        s0 += __shfl_down_sync(0xffffffffu, s0, off);
        s1 += __shfl_down_sync(0xffffffffu, s1, off);
    }
    if (lane == 0) {
        out[2 * (size_t)gw]     = s0 + __ldg(bf);
        out[2 * (size_t)gw + 1] = s1 + __ldg(bf + 1);
    }
}

// ================= launch =================
extern "C" void kernel_launch(void* const* d_in, const int* in_sizes, int n_in,
                              void* d_out, int out_size) {
    const float* x   = (const float*)d_in[0];
    const float* Ws1 = (const float*)d_in[1];
    const float* Wn1 = (const float*)d_in[2];
    const float* b1  = (const float*)d_in[3];
    const float* Ws2 = (const float*)d_in[4];
    const float* Wn2 = (const float*)d_in[5];
    const float* b2  = (const float*)d_in[6];
    const float* Wf  = (const float*)d_in[7];
    const float* bf  = (const float*)d_in[8];
    const int*   src = (const int*)d_in[9];
    const int*   dst = (const int*)d_in[10];
    float* out = (float*)d_out;

    int n  = in_sizes[0] / FEAT;
    int nE = in_sizes[9];
    int nb = (n + 1023) / 1024;
    int nTiles = (n + BR - 1) / BR;

    cudaFuncSetAttribute(sage_gemm_kernel,
                         cudaFuncAttributeMaxDynamicSharedMemorySize, GEMM_SMEM_BYTES);

    void* p_h = 0;
    cudaGetSymbolAddress(&p_h, g_h);
    float* h = (float*)p_h;

    // ---- CSR build ----
    zero_kernel<<<(n + 255) / 256, 256>>>(n, nb);
    hist_kernel<<<(nE + 255) / 256, 256>>>(dst, nE);
    scan_kernel<<<nb, 1024>>>(n);
    fill_kernel<<<(nE + 255) / 256, 256>>>(src, dst, nE);

    int gatherBlocks = (n + 7) / 8;

    // layer 1
    gather_kernel<<<gatherBlocks, 256>>>(x, n);
    sage_gemm_kernel<<<148, 512, GEMM_SMEM_BYTES>>>(x, Ws1, Wn1, b1, h, n, nTiles, 0);

    // layer 2
    gather_kernel<<<gatherBlocks, 256>>>(h, n);
    sage_gemm_kernel<<<148, 512, GEMM_SMEM_BYTES>>>(h, Ws2, Wn2, b2, h, n, nTiles, 1);

    // final projection
    final_kernel<<<(n + 7) / 8, 256>>>(Wf, bf, out, n);
}